// round 2
// baseline (speedup 1.0000x reference)
#include <cuda_runtime.h>
#include <math.h>

// Problem constants (fixed by the reference)
#define B_DIM 8
#define Q_DIM 64
#define N_DIM 8192
#define K_DIM 512
#define C_DIM 256
#define GAMMA 0.25f

// ---- scratch: per-block partial sums (deterministic final reduce) ----
#define VQ_BLOCKS  (B_DIM * (N_DIM / 128))   // 512
#define REC_BLOCKS (B_DIM * (N_DIM / 256))   // 256
#define N_PARTIALS (VQ_BLOCKS + REC_BLOCKS)  // 768
__device__ float g_partials[N_PARTIALS];

// -------------------- block reduce helper --------------------
template <int NWARPS>
__device__ __forceinline__ float block_sum(float v, float* red) {
    #pragma unroll
    for (int off = 16; off > 0; off >>= 1)
        v += __shfl_down_sync(0xFFFFFFFFu, v, off);
    int lane = threadIdx.x & 31;
    int wid  = threadIdx.x >> 5;
    if (lane == 0) red[wid] = v;
    __syncthreads();
    if (wid == 0) {
        v = (lane < NWARPS) ? red[lane] : 0.0f;
        #pragma unroll
        for (int off = 16; off > 0; off >>= 1)
            v += __shfl_down_sync(0xFFFFFFFFu, v, off);
    }
    return v;  // valid in thread 0
}

// -------------------- VQ kernel --------------------
// grid = B * (N/128), block = 128. Each thread owns one n column.
#define VQ_THREADS 128
#define KC 128   // K chunk held in smem (KC*Q*4 = 32 KB)

__global__ __launch_bounds__(VQ_THREADS)
void vq_kernel(const float* __restrict__ ze, const float* __restrict__ emb) {
    __shared__ float es[KC * Q_DIM];    // 32 KB emb chunk
    __shared__ float emb2s[K_DIM];      // 2 KB  ||emb_k||^2
    __shared__ float red[VQ_THREADS / 32];

    const int tid   = threadIdx.x;
    const int blk   = blockIdx.x;
    const int b     = blk >> 6;         // blk / (N/128)
    const int ntile = blk & 63;
    const int n     = ntile * VQ_THREADS + tid;

    // Load this thread's ze column (coalesced across the warp per q) + ||ze||^2
    const float* zp = ze + (size_t)b * Q_DIM * N_DIM + n;
    float z[Q_DIM];
    float ze2 = 0.0f;
    #pragma unroll
    for (int q = 0; q < Q_DIM; q++) {
        float v = zp[(size_t)q * N_DIM];
        z[q] = v;
        ze2 = fmaf(v, v, ze2);
    }

    // ||emb_k||^2 for all k (each thread does K/128 rows; emb is tiny, L2-hot)
    for (int k = tid; k < K_DIM; k += VQ_THREADS) {
        const float* ep = emb + k * Q_DIM;
        float s0 = 0.f, s1 = 0.f;
        #pragma unroll
        for (int q = 0; q < Q_DIM; q += 2) {
            s0 = fmaf(ep[q],     ep[q],     s0);
            s1 = fmaf(ep[q + 1], ep[q + 1], s1);
        }
        emb2s[k] = s0 + s1;
    }

    float best = 3.4e38f;

    for (int kc = 0; kc < K_DIM; kc += KC) {
        __syncthreads();  // emb2s ready (first iter) / prior es reads done
        // cooperative flat copy of the emb chunk (coalesced float4)
        {
            const float4* src = (const float4*)(emb + (size_t)kc * Q_DIM);
            float4*       dst = (float4*)es;
            #pragma unroll
            for (int i = 0; i < (KC * Q_DIM / 4) / VQ_THREADS; i++)
                dst[tid + i * VQ_THREADS] = src[tid + i * VQ_THREADS];
        }
        __syncthreads();

        #pragma unroll 2
        for (int k = 0; k < KC; k++) {
            const float4* ek = (const float4*)(es + k * Q_DIM);
            float a0 = 0.f, a1 = 0.f, a2 = 0.f, a3 = 0.f;
            #pragma unroll
            for (int qq = 0; qq < Q_DIM / 4; qq++) {
                float4 e = ek[qq];   // broadcast LDS.128 (all lanes same addr)
                a0 = fmaf(z[4 * qq + 0], e.x, a0);
                a1 = fmaf(z[4 * qq + 1], e.y, a1);
                a2 = fmaf(z[4 * qq + 2], e.z, a2);
                a3 = fmaf(z[4 * qq + 3], e.w, a3);
            }
            float d = emb2s[kc + k] - 2.0f * ((a0 + a1) + (a2 + a3));
            best = fminf(best, d);
        }
    }

    // min squared distance; l2 + gamma*commit both equal d_min in forward value
    float val = (1.0f + GAMMA) * (best + ze2);

    float s = block_sum<VQ_THREADS / 32>(val, red);
    if (tid == 0) g_partials[blk] = s;
}

// -------------------- reconstruction CE kernel --------------------
// grid = B * (N/256), block = 256. One thread per n; online logsumexp over C.
#define REC_THREADS 256

__global__ __launch_bounds__(REC_THREADS)
void rec_kernel(const float* __restrict__ qp, const int* __restrict__ tw) {
    __shared__ float red[REC_THREADS / 32];

    const int tid   = threadIdx.x;
    const int blk   = blockIdx.x;
    const int b     = blk >> 5;         // blk / (N/256)
    const int ntile = blk & 31;
    const int n     = ntile * REC_THREADS + tid;

    const float* base = qp + (size_t)b * C_DIM * N_DIM + n;

    float m = -3.4e38f, s = 0.0f;
    #pragma unroll 4
    for (int c = 0; c < C_DIM; c++) {
        float x = base[(size_t)c * N_DIM];
        if (x > m) { s *= __expf(m - x); m = x; }
        s += __expf(x - m);
    }

    // target index: int32 buffer (JAX silently downcasts int64 -> int32).
    // Clamp defensively so a bad value can never fault.
    int t = tw[(size_t)b * N_DIM + n];
    t = min(max(t, 0), C_DIM - 1);

    float lse = m + __logf(s);
    float rec = lse - base[(size_t)t * N_DIM];

    float ssum = block_sum<REC_THREADS / 32>(rec, red);
    if (tid == 0) g_partials[VQ_BLOCKS + blk] = ssum;
}

// -------------------- final deterministic reduction --------------------
__global__ void final_kernel(float* __restrict__ out) {
    __shared__ float sm[256];
    float s = 0.0f;
    for (int i = threadIdx.x; i < N_PARTIALS; i += 256)
        s += g_partials[i];
    sm[threadIdx.x] = s;
    __syncthreads();
    #pragma unroll
    for (int off = 128; off > 0; off >>= 1) {
        if (threadIdx.x < off) sm[threadIdx.x] += sm[threadIdx.x + off];
        __syncthreads();
    }
    if (threadIdx.x == 0) out[0] = sm[0];
}

// -------------------- launch --------------------
extern "C" void kernel_launch(void* const* d_in, const int* in_sizes, int n_in,
                              void* d_out, int out_size) {
    const float* ze  = (const float*)d_in[0];   // (B,Q,N)
    const float* emb = (const float*)d_in[1];   // (K,Q)
    const float* qp  = (const float*)d_in[2];   // (B,C,N)
    const int*   tw  = (const int*)d_in[3];     // (B,N) int32
    float* out = (float*)d_out;

    vq_kernel<<<VQ_BLOCKS, VQ_THREADS>>>(ze, emb);
    rec_kernel<<<REC_BLOCKS, REC_THREADS>>>(qp, tw);
    final_kernel<<<1, 256>>>(out);
}

// round 4
// speedup vs baseline: 4.6226x; 4.6226x over previous
#include <cuda_runtime.h>
#include <cuda_bf16.h>
#include <stdint.h>
#include <math.h>

#define B_DIM 8
#define Q_DIM 64
#define N_DIM 8192
#define K_DIM 512
#define C_DIM 256

#define VQ_GRID 296          // persistent CTAs (2 per SM)
#define N_TILES 1024         // (B*N)/64 tiles of 64 n-columns
#define REC_BLOCKS 256
#define NP (VQ_GRID + REC_BLOCKS)

__device__ __align__(16) __nv_bfloat16 g_emb_bf[K_DIM * Q_DIM];
__device__ float g_emb2[K_DIM];
__device__ float g_partials[NP];

// ---------------- smem layout (bytes) ----------------
// rows padded to 144B (= 9 x 16B): conflict-free ldmatrix, 16B-aligned chunks
#define EPAD 144
#define SM_RED  0                      // 16B  (4 floats)
#define SM_Z2   16                     // 512B (128 floats: two half-sums per col)
#define SM_E2   (SM_Z2 + 512)          // 2048B (||emb_k||^2)
#define SM_ZET  (SM_E2 + 2048)         // 64 * 144 = 9216B  (zeT[n][q] bf16)
#define SM_EMB  (SM_ZET + 64 * EPAD)   // 512 * 144 = 73728B (emb[k][q] bf16)
#define SMEM_TOTAL (SM_EMB + K_DIM * EPAD)   // 85504B

// ---------------- helpers ----------------
__device__ __forceinline__ uint32_t smem_u32(const void* p) {
    uint32_t a;
    asm("{ .reg .u64 t; cvta.to.shared.u64 t, %1; cvt.u32.u64 %0, t; }" : "=r"(a) : "l"(p));
    return a;
}

#define LDSM_X4(r0, r1, r2, r3, addr) \
    asm volatile("ldmatrix.sync.aligned.m8n8.x4.shared.b16 {%0,%1,%2,%3}, [%4];" \
                 : "=r"(r0), "=r"(r1), "=r"(r2), "=r"(r3) : "r"(addr))

#define MMA_BF16(a0, a1, a2, a3, b0, b1, c0, c1, c2, c3) \
    asm volatile("mma.sync.aligned.m16n8k16.row.col.f32.bf16.bf16.f32 " \
                 "{%0,%1,%2,%3}, {%4,%5,%6,%7}, {%8,%9}, {%0,%1,%2,%3};" \
                 : "+f"(c0), "+f"(c1), "+f"(c2), "+f"(c3) \
                 : "r"(a0), "r"(a1), "r"(a2), "r"(a3), "r"(b0), "r"(b1))

__device__ __forceinline__ float block_sum(float v, float* red, int nwarps) {
    #pragma unroll
    for (int off = 16; off > 0; off >>= 1)
        v += __shfl_down_sync(0xFFFFFFFFu, v, off);
    int lane = threadIdx.x & 31;
    int wid  = threadIdx.x >> 5;
    if (lane == 0) red[wid] = v;
    __syncthreads();
    if (wid == 0) {
        v = (lane < nwarps) ? red[lane] : 0.0f;
        #pragma unroll
        for (int off = 16; off > 0; off >>= 1)
            v += __shfl_down_sync(0xFFFFFFFFu, v, off);
    }
    return v;  // valid in thread 0
}

// -------------------- emb prep: fp32 -> bf16 + ||emb||^2 --------------------
__global__ void prep_emb(const float* __restrict__ emb) {
    int k = blockIdx.x;       // 512
    int q = threadIdx.x;      // 64
    float v = emb[k * Q_DIM + q];
    g_emb_bf[k * Q_DIM + q] = __float2bfloat16_rn(v);
    float sq = v * v;
    #pragma unroll
    for (int off = 16; off > 0; off >>= 1)
        sq += __shfl_down_sync(0xFFFFFFFFu, sq, off);
    __shared__ float s2[2];
    if ((q & 31) == 0) s2[q >> 5] = sq;
    __syncthreads();
    if (q == 0) g_emb2[k] = s2[0] + s2[1];
}

// -------------------- VQ distance GEMM via mma.sync (HMMA bf16) --------------------
__global__ __launch_bounds__(128) void vq_gemm(const float* __restrict__ ze) {
    extern __shared__ char smem[];
    const uint32_t sb = smem_u32(smem);
    const int tid  = threadIdx.x;
    const int lane = tid & 31;
    const int wid  = tid >> 5;

    float* red = (float*)(smem + SM_RED);
    float* z2s = (float*)(smem + SM_Z2);

    // ---- one-time: emb (bf16) -> padded smem rows; emb2 -> smem ----
    {
        const uint4* esrc = (const uint4*)g_emb_bf;   // 4096 16B units, 8 per row
        #pragma unroll
        for (int it = 0; it < 32; it++) {
            int u = tid + 128 * it;
            uint4 v = esrc[u];
            int r = u >> 3, j = u & 7;
            *(uint4*)(smem + SM_EMB + r * EPAD + j * 16) = v;
        }
        float* e2 = (float*)(smem + SM_E2);
        #pragma unroll
        for (int i = 0; i < K_DIM / 128; i++) e2[tid + 128 * i] = g_emb2[tid + 128 * i];
    }

    const float* e2s = (const float*)(smem + SM_E2);
    float acc_out = 0.0f;

    for (int tile = blockIdx.x; tile < N_TILES; tile += VQ_GRID) {
        const int b  = tile >> 7;
        const int n0 = (tile & 127) << 6;
        const float* zp = ze + (size_t)b * Q_DIM * N_DIM + n0;

        __syncthreads();   // smem reuse guard (covers first-iter emb init too)

        // ---- load ze tile, transpose to zeT[n][q] bf16, exact fp32 ze2 ----
        {
            const int c  = tid & 63;    // column n within tile
            const int qh = tid >> 6;    // q parity (0/1)
            float z2 = 0.0f;
            #pragma unroll
            for (int i = 0; i < 32; i++) {
                int q = 2 * i + qh;
                float v = zp[(size_t)q * N_DIM + c];
                z2 = fmaf(v, v, z2);
                *(__nv_bfloat16*)(smem + SM_ZET + c * EPAD + q * 2) = __float2bfloat16_rn(v);
            }
            z2s[qh * 64 + c] = z2;      // ze2[c] = z2s[c] + z2s[64+c]
        }
        __syncthreads();

        // ---- A fragments: zeT rows [16*wid, 16*wid+16), all 4 k-steps ----
        uint32_t a[4][4];
        {
            uint32_t abase = sb + SM_ZET + (uint32_t)(16 * wid + (lane & 15)) * EPAD
                           + (uint32_t)(lane >> 4) * 16u;
            #pragma unroll
            for (int ks = 0; ks < 4; ks++)
                LDSM_X4(a[ks][0], a[ks][1], a[ks][2], a[ks][3], abase + ks * 32u);
        }

        float vmin0 = 3.4e38f, vmin1 = 3.4e38f;
        const uint32_t bbase = sb + SM_EMB + (uint32_t)(lane & 7) * EPAD
                             + (uint32_t)(lane >> 3) * 16u;

        #pragma unroll 2
        for (int ct = 0; ct < 64; ct++) {     // 8 codewords per iteration
            float c0 = 0.f, c1 = 0.f, c2 = 0.f, c3 = 0.f;
            #pragma unroll
            for (int kp = 0; kp < 2; kp++) {  // k-pairs: 32 q per x4 load
                uint32_t b0, b1, b2, b3;
                LDSM_X4(b0, b1, b2, b3, bbase + (uint32_t)ct * (8u * EPAD) + kp * 64u);
                MMA_BF16(a[2 * kp][0],     a[2 * kp][1],     a[2 * kp][2],     a[2 * kp][3],     b0, b1, c0, c1, c2, c3);
                MMA_BF16(a[2 * kp + 1][0], a[2 * kp + 1][1], a[2 * kp + 1][2], a[2 * kp + 1][3], b2, b3, c0, c1, c2, c3);
            }
            float2 e2 = *(const float2*)(e2s + ct * 8 + 2 * (lane & 3));
            vmin0 = fminf(vmin0, fminf(fmaf(-2.0f, c0, e2.x), fmaf(-2.0f, c1, e2.y)));
            vmin1 = fminf(vmin1, fminf(fmaf(-2.0f, c2, e2.x), fmaf(-2.0f, c3, e2.y)));
        }

        // min across the 4 lanes of each row-quad
        vmin0 = fminf(vmin0, __shfl_xor_sync(0xFFFFFFFFu, vmin0, 1));
        vmin0 = fminf(vmin0, __shfl_xor_sync(0xFFFFFFFFu, vmin0, 2));
        vmin1 = fminf(vmin1, __shfl_xor_sync(0xFFFFFFFFu, vmin1, 1));
        vmin1 = fminf(vmin1, __shfl_xor_sync(0xFFFFFFFFu, vmin1, 2));

        float part = 0.0f;
        if ((lane & 3) == 0) {
            int r0 = 16 * wid + (lane >> 2);       // n rows r0 and r0+8
            float ze2a = z2s[r0] + z2s[64 + r0];
            float ze2b = z2s[r0 + 8] + z2s[64 + r0 + 8];
            part = 1.25f * (vmin0 + ze2a) + 1.25f * (vmin1 + ze2b);
        }
        float s = block_sum(part, red, 4);
        if (tid == 0) acc_out += s;
    }

    if (tid == 0) g_partials[blockIdx.x] = acc_out;
}

// -------------------- reconstruction CE --------------------
#define REC_THREADS 256
__global__ __launch_bounds__(REC_THREADS)
void rec_kernel(const float* __restrict__ qp, const int* __restrict__ tw) {
    __shared__ float red[REC_THREADS / 32];
    const int tid   = threadIdx.x;
    const int blk   = blockIdx.x;
    const int b     = blk >> 5;
    const int ntile = blk & 31;
    const int n     = ntile * REC_THREADS + tid;

    const float* base = qp + (size_t)b * C_DIM * N_DIM + n;

    float m = -3.4e38f, s = 0.0f;
    #pragma unroll 4
    for (int c = 0; c < C_DIM; c++) {
        float x = base[(size_t)c * N_DIM];
        if (x > m) { s *= __expf(m - x); m = x; }
        s += __expf(x - m);
    }
    int t = tw[(size_t)b * N_DIM + n];
    t = min(max(t, 0), C_DIM - 1);
    float rec = (m + __logf(s)) - base[(size_t)t * N_DIM];

    float ssum = block_sum(rec, red, REC_THREADS / 32);
    if (tid == 0) g_partials[VQ_GRID + blk] = ssum;
}

// -------------------- final deterministic reduction --------------------
__global__ void final_kernel(float* __restrict__ out) {
    __shared__ float sm[256];
    float s = 0.0f;
    for (int i = threadIdx.x; i < NP; i += 256)
        s += g_partials[i];
    sm[threadIdx.x] = s;
    __syncthreads();
    #pragma unroll
    for (int off = 128; off > 0; off >>= 1) {
        if (threadIdx.x < off) sm[threadIdx.x] += sm[threadIdx.x + off];
        __syncthreads();
    }
    if (threadIdx.x == 0) out[0] = sm[0];
}

// -------------------- launch --------------------
extern "C" void kernel_launch(void* const* d_in, const int* in_sizes, int n_in,
                              void* d_out, int out_size) {
    const float* ze  = (const float*)d_in[0];   // (B,Q,N)
    const float* emb = (const float*)d_in[1];   // (K,Q)
    const float* qp  = (const float*)d_in[2];   // (B,C,N)
    const int*   tw  = (const int*)d_in[3];     // (B,N) int32
    float* out = (float*)d_out;

    cudaFuncSetAttribute(vq_gemm, cudaFuncAttributeMaxDynamicSharedMemorySize, SMEM_TOTAL);

    prep_emb<<<K_DIM, Q_DIM>>>(emb);
    vq_gemm<<<VQ_GRID, 128, SMEM_TOTAL>>>(ze);
    rec_kernel<<<REC_BLOCKS, REC_THREADS>>>(qp, tw);
    final_kernel<<<1, 256>>>(out);
}